// round 1
// baseline (speedup 1.0000x reference)
#include <cuda_runtime.h>
#include <cstdint>

// Problem constants (from reference): S=64 per dim, key = ((x*64+y)*64+z)*64+b in [0, 2^24)
constexpr int KEYSPACE     = 1 << 24;          // 64^4
constexpr int WORDS        = KEYSPACE / 32;    // 524288 bitmap words (2 MB)
constexpr int SCAN_BLOCKS  = 512;
constexpr int SCAN_THREADS = 256;
constexpr int WPT          = WORDS / (SCAN_BLOCKS * SCAN_THREADS); // 4 words/thread

__device__ unsigned g_bitmap[WORDS];   // presence bits per key
__device__ unsigned g_rank[WORDS];     // exclusive prefix popcount at each word
__device__ unsigned g_bsums[SCAN_BLOCKS];

// ---------------------------------------------------------------------------
__global__ void k_zero_out(float4* out, int n4) {
    int i = blockIdx.x * blockDim.x + threadIdx.x;
    if (i < n4) out[i] = make_float4(0.f, 0.f, 0.f, 0.f);
}

__global__ void k_zero_bitmap() {
    int i = blockIdx.x * blockDim.x + threadIdx.x;   // WORDS/4 threads
    reinterpret_cast<uint4*>(g_bitmap)[i] = make_uint4(0u, 0u, 0u, 0u);
}

// ---------------------------------------------------------------------------
__device__ __forceinline__ unsigned make_key(int4 c) {
    return ((unsigned)((c.x * 64 + c.y) * 64 + c.z)) * 64u + (unsigned)c.w;
}

__global__ void k_setbits(const int4* __restrict__ coords, int n) {
    int i = blockIdx.x * blockDim.x + threadIdx.x;
    if (i >= n) return;
    unsigned key = make_key(coords[i]);
    atomicOr(&g_bitmap[key >> 5], 1u << (key & 31));
}

// ---------------------------------------------------------------------------
// Block-wide exclusive scan (works for up to 1024 threads, blockDim multiple of 32)
__device__ __forceinline__ unsigned block_excl_scan(unsigned v, unsigned* sh) {
    unsigned lane = threadIdx.x & 31;
    unsigned wid  = threadIdx.x >> 5;
    unsigned x = v;
    #pragma unroll
    for (int o = 1; o < 32; o <<= 1) {
        unsigned y = __shfl_up_sync(0xFFFFFFFFu, x, o);
        if (lane >= o) x += y;
    }
    if (lane == 31) sh[wid] = x;          // inclusive warp sums
    __syncthreads();
    if (wid == 0) {
        unsigned nw = blockDim.x >> 5;
        unsigned w = (lane < nw) ? sh[lane] : 0u;
        #pragma unroll
        for (int o = 1; o < 32; o <<= 1) {
            unsigned y = __shfl_up_sync(0xFFFFFFFFu, w, o);
            if (lane >= o) w += y;
        }
        if (lane < nw) sh[lane] = w;      // inclusive scan of warp sums
    }
    __syncthreads();
    unsigned warp_prefix = (wid > 0) ? sh[wid - 1] : 0u;
    return warp_prefix + x - v;           // exclusive
}

// Pass A: per-block popcount sums
__global__ void k_scan_a() {
    __shared__ unsigned sh[32];
    int t = blockIdx.x * SCAN_THREADS + threadIdx.x;
    uint4 w = reinterpret_cast<const uint4*>(g_bitmap)[t];   // WPT==4
    unsigned sum = __popc(w.x) + __popc(w.y) + __popc(w.z) + __popc(w.w);
    // block reduce via scan (cheap enough; reuse helper)
    unsigned excl = block_excl_scan(sum, sh);
    if (threadIdx.x == SCAN_THREADS - 1)
        g_bsums[blockIdx.x] = excl + sum;                    // block total
}

// Pass B: exclusive scan of the 512 block sums (single block of 512 threads)
__global__ void k_scan_b() {
    __shared__ unsigned sh[32];
    unsigned v = g_bsums[threadIdx.x];
    unsigned e = block_excl_scan(v, sh);
    g_bsums[threadIdx.x] = e;
}

// Pass C: write word-granularity exclusive prefix popcount
__global__ void k_scan_c() {
    __shared__ unsigned sh[32];
    int t = blockIdx.x * SCAN_THREADS + threadIdx.x;
    uint4 w = reinterpret_cast<const uint4*>(g_bitmap)[t];
    unsigned p0 = __popc(w.x), p1 = __popc(w.y), p2 = __popc(w.z), p3 = __popc(w.w);
    unsigned sum  = p0 + p1 + p2 + p3;
    unsigned excl = block_excl_scan(sum, sh);
    unsigned base = g_bsums[blockIdx.x] + excl;
    uint4 r;
    r.x = base;
    r.y = base + p0;
    r.z = base + p0 + p1;
    r.w = base + p0 + p1 + p2;
    reinterpret_cast<uint4*>(g_rank)[t] = r;
}

// ---------------------------------------------------------------------------
// Scatter: 8 threads per point, each handles one float4 (16B) of the 32-ch row.
// rank = prefix-popcount rank of the point's key among sorted unique keys.
__global__ void k_scatter(const int4* __restrict__ coords,
                          const float4* __restrict__ feat,
                          float* __restrict__ out, int n) {
    int t = blockIdx.x * blockDim.x + threadIdx.x;
    int p = t >> 3;
    int lane = t & 7;
    if (p >= n) return;
    unsigned key = make_key(coords[p]);
    unsigned w = key >> 5, b = key & 31;
    unsigned rank = g_rank[w] + __popc(g_bitmap[w] & ((1u << b) - 1u));
    float4 v = feat[(size_t)p * 8 + lane];
    float* dst = out + (size_t)rank * 32 + lane * 4;
    // Vectorized no-return atomic add (sm_90+): 4x fewer RED lane-ops than scalar.
    asm volatile("red.global.add.v4.f32 [%0], {%1,%2,%3,%4};"
                 :: "l"(dst), "f"(v.x), "f"(v.y), "f"(v.z), "f"(v.w)
                 : "memory");
}

// ---------------------------------------------------------------------------
extern "C" void kernel_launch(void* const* d_in, const int* in_sizes, int n_in,
                              void* d_out, int out_size) {
    const int4*   coords = (const int4*)d_in[0];    // [N,4] int32
    const float4* feat   = (const float4*)d_in[1];  // [N,32] f32 -> [N,8] float4
    float* out = (float*)d_out;                     // [N,32] f32
    int n  = in_sizes[0] / 4;
    int n4 = out_size / 4;

    k_zero_out   <<<(n4 + 255) / 256, 256>>>((float4*)d_out, n4);
    k_zero_bitmap<<<(WORDS / 4) / 256, 256>>>();
    k_setbits    <<<(n + 255) / 256, 256>>>(coords, n);
    k_scan_a     <<<SCAN_BLOCKS, SCAN_THREADS>>>();
    k_scan_b     <<<1, SCAN_BLOCKS>>>();
    k_scan_c     <<<SCAN_BLOCKS, SCAN_THREADS>>>();
    k_scatter    <<<(n * 8 + 255) / 256, 256>>>(coords, feat, out, n);
}

// round 2
// speedup vs baseline: 1.0234x; 1.0234x over previous
#include <cuda_runtime.h>
#include <cstdint>

// key = ((x*64+y)*64+z)*64+b  in [0, 2^24)
constexpr int KEYSPACE     = 1 << 24;
constexpr int WORDS        = KEYSPACE / 32;    // 524288 words (2 MB)
constexpr int SCAN_BLOCKS  = 512;
constexpr int SCAN_THREADS = 256;

__device__ unsigned g_bitmap[WORDS];   // presence bits
__device__ unsigned g_dup[WORDS];      // voxels with >=2 points
__device__ unsigned g_rank[WORDS];     // exclusive prefix popcount per word
__device__ unsigned g_bsums[SCAN_BLOCKS];
__device__ unsigned g_total;           // number of unique voxels

// ---------------------------------------------------------------------------
__global__ void k_zero_bitmaps() {
    int i = blockIdx.x * blockDim.x + threadIdx.x;   // WORDS/4 threads
    reinterpret_cast<uint4*>(g_bitmap)[i] = make_uint4(0u, 0u, 0u, 0u);
    reinterpret_cast<uint4*>(g_dup)[i]    = make_uint4(0u, 0u, 0u, 0u);
}

__device__ __forceinline__ unsigned make_key(int4 c) {
    return ((unsigned)((c.x * 64 + c.y) * 64 + c.z)) * 64u + (unsigned)c.w;
}

// Claim voxels; mark duplicates.
__global__ void k_setbits(const int4* __restrict__ coords, int n) {
    int i = blockIdx.x * blockDim.x + threadIdx.x;
    if (i >= n) return;
    unsigned key = make_key(coords[i]);
    unsigned w = key >> 5, bit = 1u << (key & 31);
    unsigned old = atomicOr(&g_bitmap[w], bit);
    if (old & bit) atomicOr(&g_dup[w], bit);   // not the first claimant
}

// ---------------------------------------------------------------------------
__device__ __forceinline__ unsigned block_excl_scan(unsigned v, unsigned* sh) {
    unsigned lane = threadIdx.x & 31;
    unsigned wid  = threadIdx.x >> 5;
    unsigned x = v;
    #pragma unroll
    for (int o = 1; o < 32; o <<= 1) {
        unsigned y = __shfl_up_sync(0xFFFFFFFFu, x, o);
        if (lane >= o) x += y;
    }
    if (lane == 31) sh[wid] = x;
    __syncthreads();
    if (wid == 0) {
        unsigned nw = blockDim.x >> 5;
        unsigned w2 = (lane < nw) ? sh[lane] : 0u;
        #pragma unroll
        for (int o = 1; o < 32; o <<= 1) {
            unsigned y = __shfl_up_sync(0xFFFFFFFFu, w2, o);
            if (lane >= o) w2 += y;
        }
        if (lane < nw) sh[lane] = w2;
    }
    __syncthreads();
    unsigned warp_prefix = (wid > 0) ? sh[wid - 1] : 0u;
    return warp_prefix + x - v;   // exclusive
}

__global__ void k_scan_a() {
    __shared__ unsigned sh[32];
    int t = blockIdx.x * SCAN_THREADS + threadIdx.x;
    uint4 w = reinterpret_cast<const uint4*>(g_bitmap)[t];
    unsigned sum = __popc(w.x) + __popc(w.y) + __popc(w.z) + __popc(w.w);
    unsigned excl = block_excl_scan(sum, sh);
    if (threadIdx.x == SCAN_THREADS - 1)
        g_bsums[blockIdx.x] = excl + sum;
}

__global__ void k_scan_b() {
    __shared__ unsigned sh[32];
    unsigned v = g_bsums[threadIdx.x];
    unsigned e = block_excl_scan(v, sh);
    g_bsums[threadIdx.x] = e;
    if (threadIdx.x == SCAN_BLOCKS - 1) g_total = e + v;   // unique count
}

__global__ void k_scan_c() {
    __shared__ unsigned sh[32];
    int t = blockIdx.x * SCAN_THREADS + threadIdx.x;
    uint4 w = reinterpret_cast<const uint4*>(g_bitmap)[t];
    unsigned p0 = __popc(w.x), p1 = __popc(w.y), p2 = __popc(w.z), p3 = __popc(w.w);
    unsigned sum  = p0 + p1 + p2 + p3;
    unsigned excl = block_excl_scan(sum, sh);
    unsigned base = g_bsums[blockIdx.x] + excl;
    uint4 r;
    r.x = base;
    r.y = base + p0;
    r.z = base + p0 + p1;
    r.w = base + p0 + p1 + p2;
    reinterpret_cast<uint4*>(g_rank)[t] = r;
}

// ---------------------------------------------------------------------------
// Zero rows of duplicated voxels (rare: ~30k rows). One thread per word.
__global__ void k_zero_dup_rows(float4* __restrict__ out) {
    int w = blockIdx.x * blockDim.x + threadIdx.x;
    if (w >= WORDS) return;
    unsigned d = g_dup[w];
    if (d == 0) return;
    unsigned bits = g_bitmap[w];
    unsigned base = g_rank[w];
    while (d) {
        int b = __ffs(d) - 1;
        d &= d - 1;
        unsigned rank = base + __popc(bits & ((1u << b) - 1u));
        float4* row = out + (size_t)rank * 8;
        float4 z = make_float4(0.f, 0.f, 0.f, 0.f);
        #pragma unroll
        for (int j = 0; j < 8; j++) row[j] = z;
    }
}

// Zero padding rows [g_total, N). Launch covers all N rows; early-out below total.
__global__ void k_zero_pad(float4* __restrict__ out, int n) {
    int i = blockIdx.x * blockDim.x + threadIdx.x;   // one per float4
    int row = i >> 3;
    if (row >= n || row < (int)g_total) return;
    out[i] = make_float4(0.f, 0.f, 0.f, 0.f);
}

// ---------------------------------------------------------------------------
// Scatter: 8 threads per point, one float4 each.
// Non-dup voxel -> plain streaming store (row fully owned by this point).
// Dup voxel     -> red.add into pre-zeroed row.
__global__ void k_scatter(const int4* __restrict__ coords,
                          const float4* __restrict__ feat,
                          float* __restrict__ out, int n) {
    int t = blockIdx.x * blockDim.x + threadIdx.x;
    int p = t >> 3;
    int lane = t & 7;
    if (p >= n) return;
    unsigned key = make_key(coords[p]);
    unsigned w = key >> 5, b = key & 31;
    unsigned rank = g_rank[w] + __popc(g_bitmap[w] & ((1u << b) - 1u));
    float4 v = feat[(size_t)p * 8 + lane];
    float* dst = out + (size_t)rank * 32 + lane * 4;
    bool dup = (g_dup[w] >> b) & 1u;
    if (!dup) {
        asm volatile("st.global.cs.v4.f32 [%0], {%1,%2,%3,%4};"
                     :: "l"(dst), "f"(v.x), "f"(v.y), "f"(v.z), "f"(v.w)
                     : "memory");
    } else {
        asm volatile("red.global.add.v4.f32 [%0], {%1,%2,%3,%4};"
                     :: "l"(dst), "f"(v.x), "f"(v.y), "f"(v.z), "f"(v.w)
                     : "memory");
    }
}

// ---------------------------------------------------------------------------
extern "C" void kernel_launch(void* const* d_in, const int* in_sizes, int n_in,
                              void* d_out, int out_size) {
    const int4*   coords = (const int4*)d_in[0];    // [N,4] int32
    const float4* feat   = (const float4*)d_in[1];  // [N,32] f32
    float* out = (float*)d_out;
    int n = in_sizes[0] / 4;

    k_zero_bitmaps<<<(WORDS / 4) / 256, 256>>>();
    k_setbits     <<<(n + 255) / 256, 256>>>(coords, n);
    k_scan_a      <<<SCAN_BLOCKS, SCAN_THREADS>>>();
    k_scan_b      <<<1, SCAN_BLOCKS>>>();
    k_scan_c      <<<SCAN_BLOCKS, SCAN_THREADS>>>();
    k_zero_dup_rows<<<(WORDS + 255) / 256, 256>>>((float4*)d_out);
    k_zero_pad    <<<(n * 8 + 255) / 256, 256>>>((float4*)d_out, n);
    k_scatter     <<<(n * 8 + 255) / 256, 256>>>(coords, feat, out, n);
}

// round 3
// speedup vs baseline: 1.0731x; 1.0486x over previous
#include <cuda_runtime.h>
#include <cstdint>

// key = ((x*64+y)*64+z)*64+b  in [0, 2^24)
constexpr int KEYSPACE     = 1 << 24;
constexpr int WORDS        = KEYSPACE / 32;       // 524288 words (2 MB)
constexpr int SCAN_THREADS = 256;                 // 1 uint4 (4 words) per thread
constexpr int SCAN_TILES   = WORDS / (4 * SCAN_THREADS);   // 512
constexpr int DUP_BLOCKS   = WORDS / 256;         // 2048
constexpr int PAD_BLOCKS   = 256;

__device__ unsigned g_bitmap[WORDS];              // presence bits
__device__ unsigned g_dup[WORDS];                 // voxels with >=2 points
__device__ uint4    g_tab[WORDS];                 // packed {bits, rank, dup, 0}
__device__ unsigned long long g_desc[SCAN_TILES]; // lookback descriptors
__device__ unsigned g_ticket;
__device__ unsigned g_total;                      // number of unique voxels

// ---------------------------------------------------------------------------
__global__ void k_zero() {
    int i = blockIdx.x * blockDim.x + threadIdx.x;      // WORDS/4 threads
    reinterpret_cast<uint4*>(g_bitmap)[i] = make_uint4(0u, 0u, 0u, 0u);
    reinterpret_cast<uint4*>(g_dup)[i]    = make_uint4(0u, 0u, 0u, 0u);
    if (i < SCAN_TILES) g_desc[i] = 0ull;
    if (i == 0) g_ticket = 0u;
}

__device__ __forceinline__ unsigned make_key(int4 c) {
    return ((unsigned)((c.x * 64 + c.y) * 64 + c.z)) * 64u + (unsigned)c.w;
}

__global__ void k_setbits(const int4* __restrict__ coords, int n) {
    int i = blockIdx.x * blockDim.x + threadIdx.x;
    if (i >= n) return;
    unsigned key = make_key(coords[i]);
    unsigned w = key >> 5, bit = 1u << (key & 31);
    unsigned old = atomicOr(&g_bitmap[w], bit);
    if (old & bit) atomicOr(&g_dup[w], bit);
}

// ---------------------------------------------------------------------------
__device__ __forceinline__ unsigned block_excl_scan(unsigned v, unsigned* sh) {
    unsigned lane = threadIdx.x & 31;
    unsigned wid  = threadIdx.x >> 5;
    unsigned x = v;
    #pragma unroll
    for (int o = 1; o < 32; o <<= 1) {
        unsigned y = __shfl_up_sync(0xFFFFFFFFu, x, o);
        if (lane >= o) x += y;
    }
    if (lane == 31) sh[wid] = x;
    __syncthreads();
    if (wid == 0) {
        unsigned nw = blockDim.x >> 5;
        unsigned w2 = (lane < nw) ? sh[lane] : 0u;
        #pragma unroll
        for (int o = 1; o < 32; o <<= 1) {
            unsigned y = __shfl_up_sync(0xFFFFFFFFu, w2, o);
            if (lane >= o) w2 += y;
        }
        if (lane < nw) sh[lane] = w2;
    }
    __syncthreads();
    unsigned warp_prefix = (wid > 0) ? sh[wid - 1] : 0u;
    return warp_prefix + x - v;   // exclusive
}

// Single-pass prefix-popcount via decoupled lookback; emits packed table.
__global__ void k_scan() {
    __shared__ unsigned sh[32];
    __shared__ unsigned sh_tile, sh_total, sh_prefix;
    if (threadIdx.x == 0) sh_tile = atomicAdd(&g_ticket, 1u);
    __syncthreads();
    unsigned tile = sh_tile;
    unsigned t = tile * SCAN_THREADS + threadIdx.x;     // uint4 index
    uint4 w = reinterpret_cast<const uint4*>(g_bitmap)[t];
    uint4 d = reinterpret_cast<const uint4*>(g_dup)[t];
    unsigned p0 = __popc(w.x), p1 = __popc(w.y), p2 = __popc(w.z), p3 = __popc(w.w);
    unsigned sum  = p0 + p1 + p2 + p3;
    unsigned excl = block_excl_scan(sum, sh);
    if (threadIdx.x == SCAN_THREADS - 1) sh_total = excl + sum;
    __syncthreads();
    unsigned T = sh_total;

    if (threadIdx.x == 0) {
        unsigned prefix = 0;
        if (tile == 0) {
            atomicExch(&g_desc[0], (2ull << 32) | (unsigned long long)T);
        } else {
            atomicExch(&g_desc[tile], (1ull << 32) | (unsigned long long)T);
            int j = (int)tile - 1;
            while (true) {
                unsigned long long dsc = atomicAdd(&g_desc[j], 0ull);
                unsigned st = (unsigned)(dsc >> 32);
                if (st == 2u) { prefix += (unsigned)dsc; break; }
                if (st == 1u) { prefix += (unsigned)dsc; --j; }
                // st == 0: spin
            }
            atomicExch(&g_desc[tile], (2ull << 32) | (unsigned long long)(prefix + T));
        }
        sh_prefix = prefix;
        if (tile == SCAN_TILES - 1) g_total = prefix + T;
    }
    __syncthreads();

    unsigned base = sh_prefix + excl;
    uint4* tab = g_tab + (size_t)t * 4;
    tab[0] = make_uint4(w.x, base,                d.x, 0u);
    tab[1] = make_uint4(w.y, base + p0,           d.y, 0u);
    tab[2] = make_uint4(w.z, base + p0 + p1,      d.z, 0u);
    tab[3] = make_uint4(w.w, base + p0 + p1 + p2, d.w, 0u);
}

// ---------------------------------------------------------------------------
// Fused: zero rows of duplicated voxels + zero padding rows [g_total, N).
__global__ void k_zero_dup_pad(float4* __restrict__ out, int n) {
    if (blockIdx.x < DUP_BLOCKS) {
        int w = blockIdx.x * 256 + threadIdx.x;
        unsigned dmask = g_dup[w];
        if (dmask == 0) return;
        uint4 e = g_tab[w];                     // {bits, rank, dup, -}
        float4 z = make_float4(0.f, 0.f, 0.f, 0.f);
        while (dmask) {
            int b = __ffs(dmask) - 1;
            dmask &= dmask - 1;
            unsigned rank = e.y + __popc(e.x & ((1u << b) - 1u));
            float4* row = out + (size_t)rank * 8;
            #pragma unroll
            for (int j = 0; j < 8; j++) row[j] = z;
        }
    } else {
        size_t start = (size_t)g_total * 8;
        size_t end   = (size_t)n * 8;
        size_t tid   = (size_t)(blockIdx.x - DUP_BLOCKS) * 256 + threadIdx.x;
        float4 z = make_float4(0.f, 0.f, 0.f, 0.f);
        for (size_t i = start + tid; i < end; i += (size_t)PAD_BLOCKS * 256)
            out[i] = z;
    }
}

// ---------------------------------------------------------------------------
// Scatter: 8 threads per point, one float4 each; ONE random 16B table load.
__global__ void k_scatter(const int4* __restrict__ coords,
                          const float4* __restrict__ feat,
                          float* __restrict__ out, int n) {
    int t = blockIdx.x * blockDim.x + threadIdx.x;
    int p = t >> 3;
    int lane = t & 7;
    if (p >= n) return;
    unsigned key = make_key(__ldg(&coords[p]));
    unsigned w = key >> 5, b = key & 31;
    uint4 e = __ldg(&g_tab[w]);                 // {bits, rank, dup, -}
    unsigned rank = e.y + __popc(e.x & ((1u << b) - 1u));
    float4 v = feat[(size_t)p * 8 + lane];
    float* dst = out + (size_t)rank * 32 + lane * 4;
    if (!((e.z >> b) & 1u)) {
        asm volatile("st.global.cs.v4.f32 [%0], {%1,%2,%3,%4};"
                     :: "l"(dst), "f"(v.x), "f"(v.y), "f"(v.z), "f"(v.w)
                     : "memory");
    } else {
        asm volatile("red.global.add.v4.f32 [%0], {%1,%2,%3,%4};"
                     :: "l"(dst), "f"(v.x), "f"(v.y), "f"(v.z), "f"(v.w)
                     : "memory");
    }
}

// ---------------------------------------------------------------------------
extern "C" void kernel_launch(void* const* d_in, const int* in_sizes, int n_in,
                              void* d_out, int out_size) {
    const int4*   coords = (const int4*)d_in[0];    // [N,4] int32
    const float4* feat   = (const float4*)d_in[1];  // [N,32] f32
    float* out = (float*)d_out;
    int n = in_sizes[0] / 4;

    k_zero        <<<(WORDS / 4) / 256, 256>>>();
    k_setbits     <<<(n + 255) / 256, 256>>>(coords, n);
    k_scan        <<<SCAN_TILES, SCAN_THREADS>>>();
    k_zero_dup_pad<<<DUP_BLOCKS + PAD_BLOCKS, 256>>>((float4*)d_out, n);
    k_scatter     <<<(n * 8 + 255) / 256, 256>>>(coords, feat, out, n);
}

// round 4
// speedup vs baseline: 1.1118x; 1.0360x over previous
#include <cuda_runtime.h>
#include <cstdint>

// key = ((x*64+y)*64+z)*64+b  in [0, 2^24)
constexpr int KEYSPACE     = 1 << 24;
constexpr int WORDS        = KEYSPACE / 32;       // 524288 words (2 MB)
constexpr int SCAN_THREADS = 256;                 // 1 uint4 (4 words) per thread
constexpr int SCAN_TILES   = WORDS / (4 * SCAN_THREADS);   // 512
constexpr int ZDP_BLOCKS   = 256;                 // split: half dup, half pad

__device__ unsigned g_bitmap[WORDS];              // presence bits
__device__ unsigned g_dup[WORDS];                 // voxels with >=2 points
__device__ uint4    g_tab[WORDS];                 // packed {bits, rank, dup, 0}
__device__ unsigned long long g_desc[SCAN_TILES]; // lookback descriptors
__device__ unsigned g_ticket;
__device__ unsigned g_total;                      // number of unique voxels
__device__ unsigned g_dup_count;                  // number of duplicated voxels
__device__ unsigned g_dup_list[1 << 20];          // ranks of duplicated voxels

// ---------------------------------------------------------------------------
__global__ void k_zero() {
    int i = blockIdx.x * blockDim.x + threadIdx.x;      // WORDS/4 threads
    reinterpret_cast<uint4*>(g_bitmap)[i] = make_uint4(0u, 0u, 0u, 0u);
    reinterpret_cast<uint4*>(g_dup)[i]    = make_uint4(0u, 0u, 0u, 0u);
    if (i < SCAN_TILES) g_desc[i] = 0ull;
    if (i == 0) { g_ticket = 0u; g_dup_count = 0u; }
}

__device__ __forceinline__ unsigned make_key(int4 c) {
    return ((unsigned)((c.x * 64 + c.y) * 64 + c.z)) * 64u + (unsigned)c.w;
}

__global__ void k_setbits(const int4* __restrict__ coords, int n) {
    int i = blockIdx.x * blockDim.x + threadIdx.x;
    if (i >= n) return;
    unsigned key = make_key(coords[i]);
    unsigned w = key >> 5, bit = 1u << (key & 31);
    unsigned old = atomicOr(&g_bitmap[w], bit);
    if (old & bit) atomicOr(&g_dup[w], bit);
}

// ---------------------------------------------------------------------------
__device__ __forceinline__ unsigned block_excl_scan(unsigned v, unsigned* sh) {
    unsigned lane = threadIdx.x & 31;
    unsigned wid  = threadIdx.x >> 5;
    unsigned x = v;
    #pragma unroll
    for (int o = 1; o < 32; o <<= 1) {
        unsigned y = __shfl_up_sync(0xFFFFFFFFu, x, o);
        if (lane >= o) x += y;
    }
    if (lane == 31) sh[wid] = x;
    __syncthreads();
    if (wid == 0) {
        unsigned nw = blockDim.x >> 5;
        unsigned w2 = (lane < nw) ? sh[lane] : 0u;
        #pragma unroll
        for (int o = 1; o < 32; o <<= 1) {
            unsigned y = __shfl_up_sync(0xFFFFFFFFu, w2, o);
            if (lane >= o) w2 += y;
        }
        if (lane < nw) sh[lane] = w2;
    }
    __syncthreads();
    unsigned warp_prefix = (wid > 0) ? sh[wid - 1] : 0u;
    return warp_prefix + x - v;   // exclusive
}

// Single-pass prefix-popcount via decoupled lookback; emits packed table and
// a compacted list of duplicated-voxel ranks.
__global__ void k_scan() {
    __shared__ unsigned sh[32];
    __shared__ unsigned sh_tile, sh_total, sh_prefix;
    if (threadIdx.x == 0) sh_tile = atomicAdd(&g_ticket, 1u);
    __syncthreads();
    unsigned tile = sh_tile;
    unsigned t = tile * SCAN_THREADS + threadIdx.x;     // uint4 index
    uint4 w = reinterpret_cast<const uint4*>(g_bitmap)[t];
    uint4 d = reinterpret_cast<const uint4*>(g_dup)[t];
    unsigned p0 = __popc(w.x), p1 = __popc(w.y), p2 = __popc(w.z), p3 = __popc(w.w);
    unsigned sum  = p0 + p1 + p2 + p3;
    unsigned excl = block_excl_scan(sum, sh);
    if (threadIdx.x == SCAN_THREADS - 1) sh_total = excl + sum;
    __syncthreads();
    unsigned T = sh_total;

    if (threadIdx.x == 0) {
        unsigned prefix = 0;
        if (tile == 0) {
            atomicExch(&g_desc[0], (2ull << 32) | (unsigned long long)T);
        } else {
            atomicExch(&g_desc[tile], (1ull << 32) | (unsigned long long)T);
            int j = (int)tile - 1;
            while (true) {
                unsigned long long dsc = atomicAdd(&g_desc[j], 0ull);
                unsigned st = (unsigned)(dsc >> 32);
                if (st == 2u) { prefix += (unsigned)dsc; break; }
                if (st == 1u) { prefix += (unsigned)dsc; --j; }
            }
            atomicExch(&g_desc[tile], (2ull << 32) | (unsigned long long)(prefix + T));
        }
        sh_prefix = prefix;
        if (tile == SCAN_TILES - 1) g_total = prefix + T;
    }
    __syncthreads();

    unsigned base = sh_prefix + excl;
    unsigned rb[4]  = { base, base + p0, base + p0 + p1, base + p0 + p1 + p2 };
    unsigned bw[4]  = { w.x, w.y, w.z, w.w };
    unsigned dw[4]  = { d.x, d.y, d.z, d.w };

    uint4* tab = g_tab + (size_t)t * 4;
    tab[0] = make_uint4(bw[0], rb[0], dw[0], 0u);
    tab[1] = make_uint4(bw[1], rb[1], dw[1], 0u);
    tab[2] = make_uint4(bw[2], rb[2], dw[2], 0u);
    tab[3] = make_uint4(bw[3], rb[3], dw[3], 0u);

    // --- compact dup ranks (warp-aggregated single atomic per warp) ---
    unsigned lane = threadIdx.x & 31;
    unsigned cnt = __popc(dw[0]) + __popc(dw[1]) + __popc(dw[2]) + __popc(dw[3]);
    unsigned incl = cnt;
    #pragma unroll
    for (int o = 1; o < 32; o <<= 1) {
        unsigned y = __shfl_up_sync(0xFFFFFFFFu, incl, o);
        if (lane >= o) incl += y;
    }
    unsigned warp_total = __shfl_sync(0xFFFFFFFFu, incl, 31);
    unsigned wbase = 0;
    if (lane == 0 && warp_total) wbase = atomicAdd(&g_dup_count, warp_total);
    wbase = __shfl_sync(0xFFFFFFFFu, wbase, 0);
    unsigned idx = wbase + incl - cnt;
    #pragma unroll
    for (int k = 0; k < 4; k++) {
        unsigned dm = dw[k];
        while (dm) {
            int b = __ffs(dm) - 1;
            dm &= dm - 1;
            g_dup_list[idx++] = rb[k] + __popc(bw[k] & ((1u << b) - 1u));
        }
    }
}

// ---------------------------------------------------------------------------
// Zero duplicated rows (compact list) + padding rows [g_total, N).
__global__ void k_zero_dup_pad(float4* __restrict__ out, int n) {
    float4 z = make_float4(0.f, 0.f, 0.f, 0.f);
    if (blockIdx.x < ZDP_BLOCKS / 2) {
        unsigned nd8 = g_dup_count * 8;
        unsigned stride = (ZDP_BLOCKS / 2) * 256;
        for (unsigned i = blockIdx.x * 256 + threadIdx.x; i < nd8; i += stride) {
            unsigned rank = g_dup_list[i >> 3];
            out[(size_t)rank * 8 + (i & 7)] = z;
        }
    } else {
        size_t start = (size_t)g_total * 8;
        size_t end   = (size_t)n * 8;
        size_t stride = (size_t)(ZDP_BLOCKS / 2) * 256;
        for (size_t i = start + (size_t)(blockIdx.x - ZDP_BLOCKS / 2) * 256 + threadIdx.x;
             i < end; i += stride)
            out[i] = z;
    }
}

// ---------------------------------------------------------------------------
// Scatter, two-stage: stage 1 computes (rank,dup) once per point into smem;
// stage 2 writes rows with 8-lane teams, feat reads fully coalesced.
__global__ void k_scatter(const int4* __restrict__ coords,
                          const float4* __restrict__ feat,
                          float* __restrict__ out, int n) {
    __shared__ unsigned s_rd[256];
    int base = blockIdx.x * 256;
    int p = base + threadIdx.x;
    if (p < n) {
        unsigned key = make_key(__ldg(&coords[p]));
        unsigned w = key >> 5, b = key & 31;
        uint4 e = __ldg(&g_tab[w]);             // {bits, rank, dup, -}
        unsigned rank = e.y + __popc(e.x & ((1u << b) - 1u));
        s_rd[threadIdx.x] = (rank << 1) | ((e.z >> b) & 1u);
    }
    __syncthreads();
    int team = threadIdx.x >> 3;
    int lane = threadIdx.x & 7;
    #pragma unroll
    for (int j = 0; j < 8; j++) {
        int pl = j * 32 + team;
        int pg = base + pl;
        if (pg < n) {
            unsigned rd = s_rd[pl];
            float4 v = feat[(size_t)pg * 8 + lane];
            float* dst = out + (size_t)(rd >> 1) * 32 + lane * 4;
            if (!(rd & 1u)) {
                asm volatile("st.global.cs.v4.f32 [%0], {%1,%2,%3,%4};"
                             :: "l"(dst), "f"(v.x), "f"(v.y), "f"(v.z), "f"(v.w)
                             : "memory");
            } else {
                asm volatile("red.global.add.v4.f32 [%0], {%1,%2,%3,%4};"
                             :: "l"(dst), "f"(v.x), "f"(v.y), "f"(v.z), "f"(v.w)
                             : "memory");
            }
        }
    }
}

// ---------------------------------------------------------------------------
extern "C" void kernel_launch(void* const* d_in, const int* in_sizes, int n_in,
                              void* d_out, int out_size) {
    const int4*   coords = (const int4*)d_in[0];    // [N,4] int32
    const float4* feat   = (const float4*)d_in[1];  // [N,32] f32
    float* out = (float*)d_out;
    int n = in_sizes[0] / 4;

    k_zero        <<<(WORDS / 4) / 256, 256>>>();
    k_setbits     <<<(n + 255) / 256, 256>>>(coords, n);
    k_scan        <<<SCAN_TILES, SCAN_THREADS>>>();
    k_zero_dup_pad<<<ZDP_BLOCKS, 256>>>((float4*)d_out, n);
    k_scatter     <<<(n + 255) / 256, 256>>>(coords, feat, out, n);
}

// round 5
// speedup vs baseline: 1.2038x; 1.0828x over previous
#include <cuda_runtime.h>
#include <cstdint>

// key = ((x*64+y)*64+z)*64+b  in [0, 2^24)
constexpr int KEYSPACE     = 1 << 24;
constexpr int WORDS        = KEYSPACE / 32;                 // 524288
constexpr int SCAN_THREADS = 256;                           // 4 words/thread
constexpr int SCAN_TILES   = WORDS / (4 * SCAN_THREADS);    // 512
constexpr int EP_BLOCKS    = 1024;                          // extras+pad kernel
constexpr unsigned KEYMASK   = 0x00FFFFFFu;
constexpr unsigned EXTRA_BIT = 0x80000000u;

__device__ unsigned g_bitmap[WORDS];             // presence bits (self-cleaned by scan)
__device__ uint2    g_tab[WORDS];                // {bits, rank}
__device__ unsigned g_key[1 << 20];              // per-point key | EXTRA_BIT
__device__ unsigned g_extra[1 << 20];            // indices of non-owner duplicate points
__device__ unsigned long long g_desc[SCAN_TILES];// lookback descriptors
__device__ unsigned g_extra_cnt;
__device__ unsigned g_total;                     // unique voxel count

// ---------------------------------------------------------------------------
__global__ void k_init() {                       // 1 block, 512 threads
    g_desc[threadIdx.x] = 0ull;
    if (threadIdx.x == 0) g_extra_cnt = 0u;
}

__device__ __forceinline__ unsigned make_key(int4 c) {
    return ((unsigned)((c.x * 64 + c.y) * 64 + c.z)) * 64u + (unsigned)c.w;
}

// Claim voxels. First claimant = owner (plain store later); later points are
// appended to the extras list and flagged in their stored key.
__global__ void k_setbits(const int4* __restrict__ coords, int n) {
    int i = blockIdx.x * blockDim.x + threadIdx.x;
    if (i >= n) return;
    unsigned key = make_key(coords[i]);
    unsigned w = key >> 5, bit = 1u << (key & 31);
    unsigned old = atomicOr(&g_bitmap[w], bit);
    if (old & bit) {
        key |= EXTRA_BIT;
        g_extra[atomicAdd(&g_extra_cnt, 1u)] = (unsigned)i;
    }
    g_key[i] = key;
}

// ---------------------------------------------------------------------------
__device__ __forceinline__ unsigned long long ld_relaxed(const unsigned long long* p) {
    unsigned long long v;
    asm volatile("ld.relaxed.gpu.global.u64 %0, [%1];" : "=l"(v) : "l"(p) : "memory");
    return v;
}

__device__ __forceinline__ unsigned block_excl_scan(unsigned v, unsigned* sh) {
    unsigned lane = threadIdx.x & 31;
    unsigned wid  = threadIdx.x >> 5;
    unsigned x = v;
    #pragma unroll
    for (int o = 1; o < 32; o <<= 1) {
        unsigned y = __shfl_up_sync(0xFFFFFFFFu, x, o);
        if (lane >= o) x += y;
    }
    if (lane == 31) sh[wid] = x;
    __syncthreads();
    if (wid == 0) {
        unsigned nw = blockDim.x >> 5;
        unsigned w2 = (lane < nw) ? sh[lane] : 0u;
        #pragma unroll
        for (int o = 1; o < 32; o <<= 1) {
            unsigned y = __shfl_up_sync(0xFFFFFFFFu, w2, o);
            if (lane >= o) w2 += y;
        }
        if (lane < nw) sh[lane] = w2;
    }
    __syncthreads();
    unsigned warp_prefix = (wid > 0) ? sh[wid - 1] : 0u;
    return warp_prefix + x - v;   // exclusive
}

// Single-pass prefix-popcount, WARP-PARALLEL decoupled lookback.
// All 512 tiles are co-resident, so blockIdx ordering cannot deadlock.
__global__ void k_scan() {
    __shared__ unsigned sh[32];
    __shared__ unsigned sh_total, sh_prefix;
    unsigned tile = blockIdx.x;
    unsigned t = tile * SCAN_THREADS + threadIdx.x;       // uint4 index
    uint4 w = reinterpret_cast<const uint4*>(g_bitmap)[t];
    reinterpret_cast<uint4*>(g_bitmap)[t] = make_uint4(0u, 0u, 0u, 0u); // self-clean
    unsigned p0 = __popc(w.x), p1 = __popc(w.y), p2 = __popc(w.z), p3 = __popc(w.w);
    unsigned sum  = p0 + p1 + p2 + p3;
    unsigned excl = block_excl_scan(sum, sh);
    if (threadIdx.x == SCAN_THREADS - 1) sh_total = excl + sum;
    __syncthreads();
    unsigned T = sh_total;

    if (threadIdx.x < 32) {
        unsigned lane = threadIdx.x;
        unsigned prefix = 0;
        if (tile == 0) {
            if (lane == 0) {
                atomicExch(&g_desc[0], (2ull << 32) | (unsigned long long)T);
                sh_prefix = 0u;
            }
        } else {
            if (lane == 0)
                atomicExch(&g_desc[tile], (1ull << 32) | (unsigned long long)T);
            int base = (int)tile - 1;
            while (true) {
                int j = base - (int)lane;
                unsigned long long d = (j >= 0) ? ld_relaxed(&g_desc[j]) : (2ull << 32);
                unsigned st = (unsigned)(d >> 32);
                unsigned m2 = __ballot_sync(0xFFFFFFFFu, st == 2u);
                unsigned m0 = __ballot_sync(0xFFFFFFFFu, st == 0u);
                int c2 = m2 ? (__ffs(m2) - 1) : 32;
                int c0 = m0 ? (__ffs(m0) - 1) : 32;
                if (c0 < c2) continue;                 // nearest pred not ready: retry window
                if (c2 < 32) {                         // prefix found within window
                    unsigned val = (lane <= (unsigned)c2) ? (unsigned)d : 0u;
                    prefix += __reduce_add_sync(0xFFFFFFFFu, val);
                    break;
                }
                prefix += __reduce_add_sync(0xFFFFFFFFu, (unsigned)d);  // all aggregates
                base -= 32;
            }
            if (lane == 0) {
                atomicExch(&g_desc[tile],
                           (2ull << 32) | (unsigned long long)(prefix + T));
                sh_prefix = prefix;
                if (tile == SCAN_TILES - 1) g_total = prefix + T;
            }
        }
    }
    __syncthreads();

    unsigned base = sh_prefix + excl;
    uint4* tp = reinterpret_cast<uint4*>(g_tab + (size_t)t * 4);
    tp[0] = make_uint4(w.x, base,           w.y, base + p0);
    tp[1] = make_uint4(w.z, base + p0 + p1, w.w, base + p0 + p1 + p2);
}

// ---------------------------------------------------------------------------
// Scatter: owners only, pure streaming stores. Stage 1 computes rank once per
// point; stage 2 writes 128B rows with 8-lane teams, feat reads coalesced.
__global__ void k_scatter(const float4* __restrict__ feat,
                          float* __restrict__ out, int n) {
    __shared__ unsigned s_rd[256];
    int base = blockIdx.x * 256;
    int p = base + threadIdx.x;
    unsigned rd = 0xFFFFFFFFu;
    if (p < n) {
        unsigned k = g_key[p];
        if (!(k & EXTRA_BIT)) {
            unsigned w = k >> 5, b = k & 31;
            uint2 e = __ldg(&g_tab[w]);               // {bits, rank}
            rd = e.y + __popc(e.x & ((1u << b) - 1u));
        }
    }
    s_rd[threadIdx.x] = rd;
    __syncthreads();
    int team = threadIdx.x >> 3;
    int lane = threadIdx.x & 7;
    #pragma unroll
    for (int j = 0; j < 8; j++) {
        int pl = j * 32 + team;
        int pg = base + pl;
        if (pg < n) {
            unsigned r = s_rd[pl];
            if (r != 0xFFFFFFFFu) {
                float4 v = __ldcs(&feat[(size_t)pg * 8 + lane]);
                float* dst = out + (size_t)r * 32 + lane * 4;
                asm volatile("st.global.cs.v4.f32 [%0], {%1,%2,%3,%4};"
                             :: "l"(dst), "f"(v.x), "f"(v.y), "f"(v.z), "f"(v.w)
                             : "memory");
            }
        }
    }
}

// ---------------------------------------------------------------------------
// Extras (red.add onto owner-written rows) + zero padding rows [g_total, N).
__global__ void k_extras_pad(const float4* __restrict__ feat,
                             float* __restrict__ out, int n) {
    if (blockIdx.x < EP_BLOCKS / 2) {
        unsigned tot = g_extra_cnt * 8u;
        unsigned stride = (EP_BLOCKS / 2) * 256;
        for (unsigned i = blockIdx.x * 256 + threadIdx.x; i < tot; i += stride) {
            unsigned p = g_extra[i >> 3];
            int lane = i & 7;
            unsigned k = g_key[p] & KEYMASK;
            unsigned w = k >> 5, b = k & 31;
            uint2 e = __ldg(&g_tab[w]);
            unsigned r = e.y + __popc(e.x & ((1u << b) - 1u));
            float4 v = __ldg(&feat[(size_t)p * 8 + lane]);
            float* dst = out + (size_t)r * 32 + lane * 4;
            asm volatile("red.global.add.v4.f32 [%0], {%1,%2,%3,%4};"
                         :: "l"(dst), "f"(v.x), "f"(v.y), "f"(v.z), "f"(v.w)
                         : "memory");
        }
    } else {
        float4 z = make_float4(0.f, 0.f, 0.f, 0.f);
        size_t start  = (size_t)g_total * 8;
        size_t end    = (size_t)n * 8;
        size_t stride = (size_t)(EP_BLOCKS / 2) * 256;
        for (size_t i = start + (size_t)(blockIdx.x - EP_BLOCKS / 2) * 256 + threadIdx.x;
             i < end; i += stride)
            reinterpret_cast<float4*>(out)[i] = z;
    }
}

// ---------------------------------------------------------------------------
extern "C" void kernel_launch(void* const* d_in, const int* in_sizes, int n_in,
                              void* d_out, int out_size) {
    const int4*   coords = (const int4*)d_in[0];    // [N,4] int32
    const float4* feat   = (const float4*)d_in[1];  // [N,32] f32
    float* out = (float*)d_out;
    int n = in_sizes[0] / 4;

    k_init      <<<1, SCAN_TILES>>>();
    k_setbits   <<<(n + 255) / 256, 256>>>(coords, n);
    k_scan      <<<SCAN_TILES, SCAN_THREADS>>>();
    k_scatter   <<<(n + 255) / 256, 256>>>(feat, out, n);
    k_extras_pad<<<EP_BLOCKS, 256>>>(feat, out, n);
}